// round 1
// baseline (speedup 1.0000x reference)
#include <cuda_runtime.h>
#include <cstdint>

// OneHotEncoder: per-row token histogram (skip pad_idx=0) -> float counts.
// tokens: [B, T] int32, out: [B, 32000] float32.

constexpr int VOCAB = 32000;
constexpr int NTHREADS = 1024;

__global__ __launch_bounds__(NTHREADS, 1)
void onehot_hist_kernel(const int* __restrict__ tokens,
                        float* __restrict__ out,
                        int T)
{
    extern __shared__ unsigned int hist[];  // VOCAB u32 = 128000 B

    const int b   = blockIdx.x;
    const int tid = threadIdx.x;

    // Phase 1: zero the histogram with 16B stores. VOCAB/4 = 8000 uint4.
    uint4 z = make_uint4(0u, 0u, 0u, 0u);
    #pragma unroll
    for (int i = tid; i < VOCAB / 4; i += NTHREADS) {
        reinterpret_cast<uint4*>(hist)[i] = z;
    }
    __syncthreads();

    // Phase 2: accumulate this row's tokens into smem (skip pad==0).
    const int* __restrict__ trow = tokens + (size_t)b * T;
    for (int i = tid; i < T; i += NTHREADS) {
        int t = trow[i];
        if (t != 0) {
            atomicAdd(&hist[t], 1u);
        }
    }
    __syncthreads();

    // Phase 3: convert to float and write the full row (coalesced float4).
    // Column 0 is naturally 0 (pad tokens skipped) -> matches reference.
    float* __restrict__ orow = out + (size_t)b * VOCAB;
    #pragma unroll
    for (int i = tid; i < VOCAB / 4; i += NTHREADS) {
        uint4 v = reinterpret_cast<const uint4*>(hist)[i];
        float4 f;
        f.x = (float)v.x;
        f.y = (float)v.y;
        f.z = (float)v.z;
        f.w = (float)v.w;
        reinterpret_cast<float4*>(orow)[i] = f;
    }
}

extern "C" void kernel_launch(void* const* d_in, const int* in_sizes, int n_in,
                              void* d_out, int out_size)
{
    const int* tokens = (const int*)d_in[0];   // [B, T] int32
    // d_in[1] = lengths [B] int32 — unused by the reference computation.

    const int B = in_sizes[1];                 // 256
    const int T = in_sizes[0] / B;             // 2048

    float* out = (float*)d_out;                // [B, VOCAB] float32

    const int smem_bytes = VOCAB * (int)sizeof(unsigned int);  // 128000
    static bool attr_set = false;
    // Idempotent attribute set (host API, not a stream op; capture-safe).
    cudaFuncSetAttribute(onehot_hist_kernel,
                         cudaFuncAttributeMaxDynamicSharedMemorySize,
                         smem_bytes);

    onehot_hist_kernel<<<B, NTHREADS, smem_bytes>>>(tokens, out, T);
}

// round 2
// speedup vs baseline: 1.1866x; 1.1866x over previous
#include <cuda_runtime.h>
#include <cstdint>

// OneHotEncoder: per-row token histogram (skip pad_idx=0) -> float counts.
// tokens: [B, T] int32, out: [B, 32000] float32.
//
// R2: packed u16 smem counters (64KB/CTA) so 3 CTAs/SM fit -> all 256 CTAs
// resident in ONE wave (was 2 waves at 128KB/CTA). Counts per bin per row
// are bounded by T=2048 < 2^16 and low-half increments cannot carry, so
// atomicAdd(u32, 1 or 1<<16) on the packed pair is exact.

constexpr int VOCAB = 32000;
constexpr int NTHREADS = 512;
constexpr int HIST_WORDS = VOCAB / 2;  // 16000 u32 = 64000 B

__global__ __launch_bounds__(NTHREADS, 3)
void onehot_hist_kernel(const int* __restrict__ tokens,
                        float* __restrict__ out,
                        int T)
{
    extern __shared__ unsigned int hist[];  // HIST_WORDS u32 (packed u16 x2)

    const int b   = blockIdx.x;
    const int tid = threadIdx.x;

    // Phase 1: zero the histogram with 16B stores. 16000/4 = 4000 uint4.
    uint4 z = make_uint4(0u, 0u, 0u, 0u);
    #pragma unroll
    for (int i = tid; i < HIST_WORDS / 4; i += NTHREADS) {
        reinterpret_cast<uint4*>(hist)[i] = z;
    }
    __syncthreads();

    // Phase 2: accumulate this row's tokens (skip pad==0).
    // Bin t lives in word t>>1, half (t&1): add 1 or 1<<16.
    const int* __restrict__ trow = tokens + (size_t)b * T;
    #pragma unroll 4
    for (int i = tid; i < T; i += NTHREADS) {
        int t = trow[i];
        if (t != 0) {
            atomicAdd(&hist[t >> 1], 1u << ((t & 1) << 4));
        }
    }
    __syncthreads();

    // Phase 3: unpack u16 pairs -> float and write the full row (float4).
    // Column 0 is naturally 0 (pad tokens skipped) -> matches reference.
    float* __restrict__ orow = out + (size_t)b * VOCAB;
    #pragma unroll
    for (int i = tid; i < VOCAB / 4; i += NTHREADS) {
        // float4 i covers vocab [4i, 4i+3] = words 2i, 2i+1.
        uint2 w = reinterpret_cast<const uint2*>(hist)[i];
        float4 f;
        f.x = (float)(w.x & 0xFFFFu);
        f.y = (float)(w.x >> 16);
        f.z = (float)(w.y & 0xFFFFu);
        f.w = (float)(w.y >> 16);
        reinterpret_cast<float4*>(orow)[i] = f;
    }
}

extern "C" void kernel_launch(void* const* d_in, const int* in_sizes, int n_in,
                              void* d_out, int out_size)
{
    const int* tokens = (const int*)d_in[0];   // [B, T] int32
    // d_in[1] = lengths [B] int32 — unused by the reference computation.

    const int B = in_sizes[1];                 // 256
    const int T = in_sizes[0] / B;             // 2048

    float* out = (float*)d_out;                // [B, VOCAB] float32

    const int smem_bytes = HIST_WORDS * (int)sizeof(unsigned int);  // 64000
    cudaFuncSetAttribute(onehot_hist_kernel,
                         cudaFuncAttributeMaxDynamicSharedMemorySize,
                         smem_bytes);

    onehot_hist_kernel<<<B, NTHREADS, smem_bytes>>>(tokens, out, T);
}